// round 3
// baseline (speedup 1.0000x reference)
#include <cuda_runtime.h>
#include <math.h>

// ---------------------------------------------------------------------------
// ConvolutionKAN as a fused dense GEMM.
//
// out[n, o] = sum_{i=0}^{287} [ sum_{c=0}^{7} basis_c(x_{n,i}) * (spline[i,c,o]*scale[i,o])
//                               + silu(x_{n,i}) * scale[i,o] ] + bias[o]
//
// Uniform cubic B-spline closed form replaces Cox-de Boor:
//   j = floor((x+1)/0.4) in [0,4], u = frac; nonzero bases at j..j+3:
//   (1-u)^3/6, (3u^3-6u^2+4)/6, (-3u^3+3u^2+3u+1)/6, u^3/6
//
// => out = A[N, 2592] @ Wc[2592, 128] + bias,  K index k = i*9 + c (c=8 is silu).
// A is constructed tile-by-tile in shared memory (never hits HBM).
// ---------------------------------------------------------------------------

#define N_TOTAL 61504   // 16 * 62 * 62
#define IN_SIZE 288
#define K_TOTAL 2592    // 288 * 9
#define FILTERS 128
#define BM 128          // n per block
#define BK 36           // k per tile (= 4 input-groups of 9)
#define KT_ITERS 72     // 2592 / 36
#define ASTRIDE 132     // padded A row stride (floats) to avoid STS bank conflicts

__device__ float g_Wc[K_TOTAL * FILTERS];   // fused weights, 1.33 MB

// --------------------------- weight fusion pass ----------------------------
__global__ void fuse_weights_kernel(const float* __restrict__ sk,   // [288,8,128]
                                    const float* __restrict__ sc) { // [288,128]
    int idx = blockIdx.x * 256 + threadIdx.x;
    if (idx >= K_TOTAL * FILTERS) return;
    int o = idx & (FILTERS - 1);
    int k = idx >> 7;
    int i = k / 9;
    int c = k - i * 9;
    float s = sc[i * FILTERS + o];
    g_Wc[idx] = (c < 8) ? sk[(i * 8 + c) * FILTERS + o] * s : s;
}

// ------------------------------- main GEMM ---------------------------------
__global__ __launch_bounds__(256, 2)
void kan_gemm_kernel(const float* __restrict__ input,  // [16,64,64,32]
                     const float* __restrict__ bias,   // [128]
                     float* __restrict__ out) {        // [61504,128]
    __shared__ float A_s[BK * ASTRIDE];
    __shared__ float W_s[BK * FILTERS];

    const int tid = threadIdx.x;
    const int tn  = tid >> 4;            // 0..15  -> n sub-tile (8 rows)
    const int to  = tid & 15;            // 0..15  -> o sub-tile (8 cols)
    const int n_block = blockIdx.x * BM;

    // Precompute per-task patch base addresses (two A-construction tasks/thread).
    int base_addr[2];
    int valid_n[2];
#pragma unroll
    for (int h = 0; h < 2; ++h) {
        int t = tid + h * 256;           // task id 0..511
        int n_local = t >> 2;            // 0..127
        int n = n_block + n_local;
        int v = (n < N_TOTAL);
        int nc = v ? n : 0;
        int b = nc / 3844;               // 62*62
        int r = nc - b * 3844;
        int y = r / 62;
        int xx = r - y * 62;
        base_addr[h] = ((b * 64 + y) * 64 + xx) * 32;
        valid_n[h] = v;
    }

    float acc[8][8];
#pragma unroll
    for (int a = 0; a < 8; ++a)
#pragma unroll
        for (int q = 0; q < 8; ++q) acc[a][q] = 0.f;

    for (int kt = 0; kt < KT_ITERS; ++kt) {
        // ---- stage W tile: 36x128 floats = 1152 float4 (coalesced, L2-hot) ----
        const float4* wg  = reinterpret_cast<const float4*>(g_Wc + kt * BK * FILTERS);
        float4*       ws4 = reinterpret_cast<float4*>(W_s);
#pragma unroll
        for (int v = 0; v < 5; ++v) {
            int idx = tid + v * 256;
            if (idx < (BK * FILTERS) / 4) ws4[idx] = wg[idx];
        }

        // ---- build A tile: 128 n x 4 inputs x 9 features ----
        const int i0 = kt * 4;
#pragma unroll
        for (int h = 0; h < 2; ++h) {
            int t = tid + h * 256;
            int ii = t & 3;
            int n_local = t >> 2;
            int i = i0 + ii;
            int di = i / 96;
            int rj = i - di * 96;
            int dj = rj >> 5;
            int c  = rj & 31;
            float x = 0.f;
            if (valid_n[h]) x = input[base_addr[h] + (di * 64 + dj) * 32 + c];

            // uniform cubic B-spline, grid [-1,1], h = 0.4
            float tpos = (x + 1.0f) * 2.5f;
            int j = (int)floorf(tpos);
            j = max(0, min(4, j));
            float u  = tpos - (float)j;
            float um = 1.0f - u;
            float u2 = u * u;
            float u3 = u2 * u;
            float b0 = um * um * um * (1.0f / 6.0f);
            float b1 = (3.0f * u3 - 6.0f * u2 + 4.0f) * (1.0f / 6.0f);
            float b2 = (-3.0f * u3 + 3.0f * u2 + 3.0f * u + 1.0f) * (1.0f / 6.0f);
            float b3 = u3 * (1.0f / 6.0f);
            float sl = x / (1.0f + __expf(-x));     // silu

            int kb = ii * 9;
            float* Arow = A_s + n_local;
#pragma unroll
            for (int z = 0; z < 8; ++z) Arow[(kb + z) * ASTRIDE] = 0.f;
            Arow[(kb + j + 0) * ASTRIDE] = b0;
            Arow[(kb + j + 1) * ASTRIDE] = b1;
            Arow[(kb + j + 2) * ASTRIDE] = b2;
            Arow[(kb + j + 3) * ASTRIDE] = b3;
            Arow[(kb + 8) * ASTRIDE]     = sl;
        }
        __syncthreads();

        // ---- 8x8 register-tiled FMA mainloop ----
#pragma unroll 4
        for (int k = 0; k < BK; ++k) {
            float4 a0 = *reinterpret_cast<const float4*>(A_s + k * ASTRIDE + tn * 8);
            float4 a1 = *reinterpret_cast<const float4*>(A_s + k * ASTRIDE + tn * 8 + 4);
            float4 w0 = *reinterpret_cast<const float4*>(W_s + k * FILTERS + to * 8);
            float4 w1 = *reinterpret_cast<const float4*>(W_s + k * FILTERS + to * 8 + 4);
            float av[8] = {a0.x, a0.y, a0.z, a0.w, a1.x, a1.y, a1.z, a1.w};
            float wv[8] = {w0.x, w0.y, w0.z, w0.w, w1.x, w1.y, w1.z, w1.w};
#pragma unroll
            for (int a = 0; a < 8; ++a)
#pragma unroll
                for (int q = 0; q < 8; ++q)
                    acc[a][q] = fmaf(av[a], wv[q], acc[a][q]);
        }
        __syncthreads();
    }

    // ---- epilogue: add bias, vectorized stores ----
    float bi[8];
#pragma unroll
    for (int q = 0; q < 8; ++q) bi[q] = bias[to * 8 + q];

#pragma unroll
    for (int a = 0; a < 8; ++a) {
        int n = n_block + tn * 8 + a;
        if (n < N_TOTAL) {
            float4 o0, o1;
            o0.x = acc[a][0] + bi[0];
            o0.y = acc[a][1] + bi[1];
            o0.z = acc[a][2] + bi[2];
            o0.w = acc[a][3] + bi[3];
            o1.x = acc[a][4] + bi[4];
            o1.y = acc[a][5] + bi[5];
            o1.z = acc[a][6] + bi[6];
            o1.w = acc[a][7] + bi[7];
            float* op = out + (size_t)n * FILTERS + to * 8;
            *reinterpret_cast<float4*>(op)     = o0;
            *reinterpret_cast<float4*>(op + 4) = o1;
        }
    }
}

// ------------------------------- launcher ----------------------------------
extern "C" void kernel_launch(void* const* d_in, const int* in_sizes, int n_in,
                              void* d_out, int out_size) {
    const float* input = (const float*)d_in[0];   // (16,64,64,32)
    const float* sk    = (const float*)d_in[1];   // (288,8,128)
    const float* sc    = (const float*)d_in[2];   // (288,128)
    const float* bias  = (const float*)d_in[3];   // (128,)
    // d_in[4] = grid (288,12): uniform, folded into closed-form basis.
    float* out = (float*)d_out;

    (void)in_sizes; (void)n_in; (void)out_size;

    int fuse_blocks = (K_TOTAL * FILTERS + 255) / 256;
    fuse_weights_kernel<<<fuse_blocks, 256>>>(sk, sc);

    int gemm_blocks = (N_TOTAL + BM - 1) / BM;    // 481
    kan_gemm_kernel<<<gemm_blocks, 256>>>(input, bias, out);
}

// round 5
// speedup vs baseline: 2.5887x; 2.5887x over previous
#include <cuda_runtime.h>
#include <math.h>
#include <stdint.h>

// ============================================================================
// ConvolutionKAN as mma.sync tf32 GEMM (sm_100-safe, no 'a'-suffix features):
//   out[61504,128] = A[61504,2592] @ W[2592,128] + bias
//   K layout: k in [0,2304): spline (i = k>>3, basis c = k&7, uniform cubic
//             B-spline closed form, 4 of 8 nonzero); k in [2304,2592): silu.
//   A tiles (256 x 32, tf32) built on the fly in SMEM, stride-36 rows
//   (conflict-free frag loads AND full-rate builder st.v4).
//   W pre-fused + pre-permuted into m16n8k8 B-fragment order (ld.shared.v2).
// ============================================================================

#define N_TOTAL   61504
#define K_TOTAL   2592
#define FILTERS   128
#define BM        256
#define BK        32
#define NKT       81
#define NSPLINE   72
#define AST       36                    // A row stride (floats)

#define A_STAGE_FLOATS (BM * AST)       // 9216
#define W_STAGE_FLOATS 4096
#define SMEM_W_OFF     (2 * A_STAGE_FLOATS)                  // float offset
#define SMEM_TOTAL     ((2 * A_STAGE_FLOATS + 2 * W_STAGE_FLOATS) * 4)  // 106496 B

// W in fragment order: per 32-k tile: [kq(4)][oblock(16)][lane(32)][reg(2)]
//   element (k_local, o): kq=k>>3, lane=(o&7)*4+(k&3), reg=(k>>2)&1, ob=o>>3
__device__ float g_Wt[K_TOTAL * FILTERS];

// ---------------------------------------------------------------- helpers --
__device__ __forceinline__ uint32_t f2tf32(float x) {
    uint32_t r;
    asm("cvt.rna.tf32.f32 %0, %1;" : "=r"(r) : "f"(x));
    return r;
}

__device__ __forceinline__ void mma8(float* d, const uint32_t* a,
                                     uint32_t b0, uint32_t b1) {
    asm volatile(
        "mma.sync.aligned.m16n8k8.row.col.f32.tf32.tf32.f32 "
        "{%0,%1,%2,%3}, {%4,%5,%6,%7}, {%8,%9}, {%0,%1,%2,%3};"
        : "+f"(d[0]), "+f"(d[1]), "+f"(d[2]), "+f"(d[3])
        : "r"(a[0]), "r"(a[1]), "r"(a[2]), "r"(a[3]), "r"(b0), "r"(b1));
}

// --------------------------------------------------------- weight fuse -----
__global__ void fuse_weights(const float* __restrict__ sk,   // [288,8,128]
                             const float* __restrict__ sc) { // [288,128]
    int idx = blockIdx.x * 256 + threadIdx.x;
    if (idx >= K_TOTAL * FILTERS) return;
    int kt   = idx >> 12;
    int rem  = idx & 4095;
    int kq   = rem >> 10;
    int rem2 = rem & 1023;
    int ob   = rem2 >> 6;
    int l2   = rem2 & 63;
    int lane = l2 >> 1;
    int reg  = l2 & 1;
    int o    = ob * 8 + (lane >> 2);
    int k    = kt * 32 + kq * 8 + reg * 4 + (lane & 3);
    float v;
    if (k < 2304) {
        int i = k >> 3;
        v = sk[k * 128 + o] * sc[i * 128 + o];   // sk[i][c][o], k = i*8+c
    } else {
        v = sc[(k - 2304) * 128 + o];
    }
    ((uint32_t*)g_Wt)[idx] = f2tf32(v);
}

// ------------------------------------------------------------ A builder ----
__device__ __forceinline__ void build_a(int kt, float* dst,
                                        const float* __restrict__ rowbase) {
    if (kt < NSPLINE) {
        int i0  = kt * 4;
        int di  = i0 / 96;
        int rem = i0 - di * 96;
        int dj  = rem >> 5;
        int c0  = rem & 31;
        float4 xv = *reinterpret_cast<const float4*>(rowbase + (di * 64 + dj) * 32 + c0);
        float xs[4] = {xv.x, xv.y, xv.z, xv.w};
#pragma unroll
        for (int g = 0; g < 4; ++g) {
            float x  = xs[g];
            float tp = (x + 1.0f) * 2.5f;            // uniform grid, h = 0.4
            int j = (int)floorf(tp);
            j = max(0, min(4, j));
            float u  = tp - (float)j;
            float um = 1.0f - u;
            float u2 = u * u, u3 = u2 * u;
            float b0 = um * um * um * (1.0f / 6.0f);
            float b1 = (3.0f * u3 - 6.0f * u2 + 4.0f) * (1.0f / 6.0f);
            float b2 = (-3.0f * u3 + 3.0f * u2 + 3.0f * u + 1.0f) * (1.0f / 6.0f);
            float b3 = u3 * (1.0f / 6.0f);
            uint32_t v[8];
#pragma unroll
            for (int z = 0; z < 8; ++z) v[z] = 0u;
            v[j]     = f2tf32(b0);
            v[j + 1] = f2tf32(b1);
            v[j + 2] = f2tf32(b2);
            v[j + 3] = f2tf32(b3);
            uint4* p = reinterpret_cast<uint4*>(dst + g * 8);
            p[0] = make_uint4(v[0], v[1], v[2], v[3]);
            p[1] = make_uint4(v[4], v[5], v[6], v[7]);
        }
    } else {
        int ib = kt - NSPLINE;
        int di = ib / 3;
        int dj = ib - di * 3;
        const float* src = rowbase + (di * 64 + dj) * 32;
#pragma unroll
        for (int q = 0; q < 8; ++q) {
            float4 xv = *reinterpret_cast<const float4*>(src + q * 4);
            float f[4] = {xv.x, xv.y, xv.z, xv.w};
            uint32_t v[4];
#pragma unroll
            for (int z = 0; z < 4; ++z) {
                float x = f[z];
                v[z] = f2tf32(x / (1.0f + __expf(-x)));
            }
            *reinterpret_cast<uint4*>(dst + q * 4) = make_uint4(v[0], v[1], v[2], v[3]);
        }
    }
}

// -------------------------------------------------------------- main -------
__global__ __launch_bounds__(256, 1)
void kan_mma_kernel(const float* __restrict__ input,   // [16,64,64,32]
                    const float* __restrict__ bias,    // [128]
                    float* __restrict__ out) {         // [61504,128]
    extern __shared__ float smem[];
    float* Asm = smem;                 // 2 stages of 256 x 36
    float* Wsm = smem + SMEM_W_OFF;    // 2 stages of 4096

    const int tid = threadIdx.x;
    const int l   = tid & 31;
    const int wid = tid >> 5;
    const int wm  = wid >> 1;          // 0..3 : M warp row
    const int wn  = wid & 1;           // 0..1 : N warp col

    // fixed input row for the builder role of this thread
    int n = blockIdx.x * BM + tid;
    if (n >= N_TOTAL) n = N_TOTAL - 1;
    int bb = n / 3844;                  // 62*62
    int rr = n - bb * 3844;
    int yy = rr / 62;
    int xx = rr - yy * 62;
    const float* rowbase = input + ((bb * 64 + yy) * 64 + xx) * 32;
    float* arow = Asm + tid * AST;

    // accumulators initialized with bias (folds epilogue add)
    float acc[4][8][4];
#pragma unroll
    for (int nf = 0; nf < 8; ++nf) {
        int o = wn * 64 + nf * 8 + (l & 3) * 2;
        float b0 = bias[o];
        float b1 = bias[o + 1];
#pragma unroll
        for (int mf = 0; mf < 4; ++mf) {
            acc[mf][nf][0] = b0;
            acc[mf][nf][1] = b1;
            acc[mf][nf][2] = b0;
            acc[mf][nf][3] = b1;
        }
    }

    // prologue: stage 0
    {
        build_a(0, arow, rowbase);
        const float4* wg = reinterpret_cast<const float4*>(g_Wt);
        float4* ws = reinterpret_cast<float4*>(Wsm);
#pragma unroll
        for (int v = 0; v < 4; ++v) ws[tid + 256 * v] = wg[tid + 256 * v];
    }
    __syncthreads();

    for (int kt = 0; kt < NKT; ++kt) {
        const int s = kt & 1;

        // ---- build next tile into the other stage (no sync needed yet) ----
        if (kt + 1 < NKT) {
            build_a(kt + 1, arow + (s ^ 1) * A_STAGE_FLOATS, rowbase);
            const float4* wg = reinterpret_cast<const float4*>(g_Wt + (kt + 1) * W_STAGE_FLOATS);
            float4* ws = reinterpret_cast<float4*>(Wsm + (s ^ 1) * W_STAGE_FLOATS);
#pragma unroll
            for (int v = 0; v < 4; ++v) ws[tid + 256 * v] = wg[tid + 256 * v];
        }

        // ---- compute current tile ----
        const float* As = Asm + s * A_STAGE_FLOATS;
        const float* Ws = Wsm + s * W_STAGE_FLOATS;
        const float* ab = As + (wm * 64 + (l >> 2)) * AST + (l & 3);
        const float2* wb = reinterpret_cast<const float2*>(Ws) + (wn * 8) * 32 + l;

#pragma unroll
        for (int ks = 0; ks < 4; ++ks) {
            uint32_t a[4][4];
#pragma unroll
            for (int mf = 0; mf < 4; ++mf) {
                const float* p = ab + mf * (16 * AST) + ks * 8;
                a[mf][0] = __float_as_uint(p[0]);
                a[mf][1] = __float_as_uint(p[8 * AST]);
                a[mf][2] = __float_as_uint(p[4]);
                a[mf][3] = __float_as_uint(p[8 * AST + 4]);
            }
#pragma unroll
            for (int nf = 0; nf < 8; ++nf) {
                float2 bv = wb[ks * 512 + nf * 32];
                uint32_t b0 = __float_as_uint(bv.x);
                uint32_t b1 = __float_as_uint(bv.y);
#pragma unroll
                for (int mf = 0; mf < 4; ++mf)
                    mma8(acc[mf][nf], a[mf], b0, b1);
            }
        }
        __syncthreads();
    }

    // ---- epilogue: direct float2 stores (bias already folded) ----
#pragma unroll
    for (int mf = 0; mf < 4; ++mf) {
        int r0 = blockIdx.x * BM + wm * 64 + mf * 16 + (l >> 2);
#pragma unroll
        for (int nf = 0; nf < 8; ++nf) {
            int o = wn * 64 + nf * 8 + (l & 3) * 2;
            if (r0 < N_TOTAL) {
                float2 v = make_float2(acc[mf][nf][0], acc[mf][nf][1]);
                *reinterpret_cast<float2*>(out + (size_t)r0 * FILTERS + o) = v;
            }
            if (r0 + 8 < N_TOTAL) {
                float2 v = make_float2(acc[mf][nf][2], acc[mf][nf][3]);
                *reinterpret_cast<float2*>(out + (size_t)(r0 + 8) * FILTERS + o) = v;
            }
        }
    }
}

// ------------------------------------------------------------- launcher ----
extern "C" void kernel_launch(void* const* d_in, const int* in_sizes, int n_in,
                              void* d_out, int out_size) {
    const float* input = (const float*)d_in[0];   // (16,64,64,32)
    const float* sk    = (const float*)d_in[1];   // (288,8,128)
    const float* sc    = (const float*)d_in[2];   // (288,128)
    const float* bias  = (const float*)d_in[3];   // (128,)
    float* out = (float*)d_out;
    (void)in_sizes; (void)n_in; (void)out_size;

    static bool attr_done = false;
    if (!attr_done) {
        cudaFuncSetAttribute(kan_mma_kernel,
                             cudaFuncAttributeMaxDynamicSharedMemorySize, SMEM_TOTAL);
        attr_done = true;
    }

    fuse_weights<<<(K_TOTAL * FILTERS + 255) / 256, 256>>>(sk, sc);

    int blocks = (N_TOTAL + BM - 1) / BM;   // 241
    kan_mma_kernel<<<blocks, 256, SMEM_TOTAL>>>(input, bias, out);
}

// round 6
// speedup vs baseline: 2.8701x; 1.1087x over previous
#include <cuda_runtime.h>
#include <math.h>
#include <stdint.h>

// ============================================================================
// ConvolutionKAN as mma.sync tf32 GEMM (sm_100-safe):
//   out[61504,128] = A[61504,2592] @ W[2592,128] + bias
//   K layout: k in [0,2304): spline (i=k>>3, basis c=k&7, uniform cubic
//             B-spline closed form); k in [2304,2592): silu(x_i).
// R6: BM=128, warp tile 32x64, 2 CTAs/SM (regs<=128) for latency hiding.
// ============================================================================

#define N_TOTAL   61504
#define K_TOTAL   2592
#define FILTERS   128
#define BM        128
#define NKT       81
#define NSPLINE   72
#define AST       36                    // A row stride (floats)

#define A_STAGE_FLOATS (BM * AST)       // 4608
#define W_STAGE_FLOATS 4096
#define SMEM_W_OFF     (2 * A_STAGE_FLOATS)
#define SMEM_TOTAL     ((2 * A_STAGE_FLOATS + 2 * W_STAGE_FLOATS) * 4)  // 69632 B

// W in m16n8k8 B-fragment order per 32-k tile: [kq(4)][oblock(16)][lane(32)][2]
__device__ float g_Wt[K_TOTAL * FILTERS];

// ---------------------------------------------------------------- helpers --
__device__ __forceinline__ uint32_t f2tf32(float x) {
    uint32_t r;
    asm("cvt.rna.tf32.f32 %0, %1;" : "=r"(r) : "f"(x));
    return r;
}
__device__ __forceinline__ void mma8(float* d, const uint32_t* a,
                                     uint32_t b0, uint32_t b1) {
    asm volatile(
        "mma.sync.aligned.m16n8k8.row.col.f32.tf32.tf32.f32 "
        "{%0,%1,%2,%3}, {%4,%5,%6,%7}, {%8,%9}, {%0,%1,%2,%3};"
        : "+f"(d[0]), "+f"(d[1]), "+f"(d[2]), "+f"(d[3])
        : "r"(a[0]), "r"(a[1]), "r"(a[2]), "r"(a[3]), "r"(b0), "r"(b1));
}

// --------------------------------------------------------- weight fuse -----
__global__ void fuse_weights(const float* __restrict__ sk,   // [288,8,128]
                             const float* __restrict__ sc) { // [288,128]
    int idx = blockIdx.x * 256 + threadIdx.x;
    if (idx >= K_TOTAL * FILTERS) return;
    int kt   = idx >> 12;
    int rem  = idx & 4095;
    int kq   = rem >> 10;
    int rem2 = rem & 1023;
    int ob   = rem2 >> 6;
    int l2   = rem2 & 63;
    int lane = l2 >> 1;
    int reg  = l2 & 1;
    int o    = ob * 8 + (lane >> 2);
    int k    = kt * 32 + kq * 8 + reg * 4 + (lane & 3);
    float v;
    if (k < 2304) {
        int i = k >> 3;
        v = sk[k * 128 + o] * sc[i * 128 + o];
    } else {
        v = sc[(k - 2304) * 128 + o];
    }
    ((uint32_t*)g_Wt)[idx] = f2tf32(v);
}

// ------------------------------------------------------------ A builder ----
// Thread builds HALF of one row's 32-k slice: h=0 -> k[0,16), h=1 -> k[16,32).
__device__ __forceinline__ void build_a_half(int kt, int h, float* dst,
                                             const float* __restrict__ rowbase) {
    if (kt < NSPLINE) {
        // channels i0+2h, i0+2h+1 (same (di,dj,c-block) since i0 % 4 == 0)
        int i0  = kt * 4;
        int di  = i0 / 96;
        int rem = i0 - di * 96;
        int dj  = rem >> 5;
        int c0  = rem & 31;
        float2 xv = *reinterpret_cast<const float2*>(
            rowbase + (di * 64 + dj) * 32 + c0 + 2 * h);
        float xs[2] = {xv.x, xv.y};
#pragma unroll
        for (int g = 0; g < 2; ++g) {
            float x  = xs[g];
            float tp = (x + 1.0f) * 2.5f;            // uniform grid, h = 0.4
            int j = (int)floorf(tp);
            j = max(0, min(4, j));
            float u  = tp - (float)j;
            float um = 1.0f - u;
            float u2 = u * u, u3 = u2 * u;
            float b0 = um * um * um * (1.0f / 6.0f);
            float b1 = (3.0f * u3 - 6.0f * u2 + 4.0f) * (1.0f / 6.0f);
            float b2 = (-3.0f * u3 + 3.0f * u2 + 3.0f * u + 1.0f) * (1.0f / 6.0f);
            float b3 = u3 * (1.0f / 6.0f);
            uint32_t v[8];
#pragma unroll
            for (int z = 0; z < 8; ++z) v[z] = 0u;
            v[j]     = f2tf32(b0);
            v[j + 1] = f2tf32(b1);
            v[j + 2] = f2tf32(b2);
            v[j + 3] = f2tf32(b3);
            uint4* p = reinterpret_cast<uint4*>(dst + h * 16 + g * 8);
            p[0] = make_uint4(v[0], v[1], v[2], v[3]);
            p[1] = make_uint4(v[4], v[5], v[6], v[7]);
        }
    } else {
        int ib = kt - NSPLINE;
        int di = ib / 3;
        int dj = ib - di * 3;
        const float* src = rowbase + (di * 64 + dj) * 32 + h * 16;
#pragma unroll
        for (int q = 0; q < 4; ++q) {
            float4 xv = *reinterpret_cast<const float4*>(src + q * 4);
            float f[4] = {xv.x, xv.y, xv.z, xv.w};
            uint32_t v[4];
#pragma unroll
            for (int z = 0; z < 4; ++z) {
                float x = f[z];
                v[z] = f2tf32(x / (1.0f + __expf(-x)));
            }
            *reinterpret_cast<uint4*>(dst + h * 16 + q * 4) =
                make_uint4(v[0], v[1], v[2], v[3]);
        }
    }
}

// -------------------------------------------------------------- main -------
__global__ __launch_bounds__(256, 2)
void kan_mma_kernel(const float* __restrict__ input,   // [16,64,64,32]
                    const float* __restrict__ bias,    // [128]
                    float* __restrict__ out) {         // [61504,128]
    extern __shared__ float smem[];
    float* Asm = smem;                 // 2 stages of 128 x 36
    float* Wsm = smem + SMEM_W_OFF;    // 2 stages of 4096

    const int tid = threadIdx.x;
    const int l   = tid & 31;
    const int wid = tid >> 5;
    const int wm  = wid >> 1;          // 0..3 : M warp row (32 rows each)
    const int wn  = wid & 1;           // 0..1 : N warp col (64 cols each)

    // builder role: row = tid&127, k-half = tid>>7
    const int br = tid & 127;
    const int bh = tid >> 7;
    int n = blockIdx.x * BM + br;
    if (n >= N_TOTAL) n = N_TOTAL - 1;
    int bb = n / 3844;                  // 62*62
    int rr = n - bb * 3844;
    int yy = rr / 62;
    int xx = rr - yy * 62;
    const float* rowbase = input + ((bb * 64 + yy) * 64 + xx) * 32;
    float* arow = Asm + br * AST;

    // accumulators initialized with bias
    float acc[2][8][4];
#pragma unroll
    for (int nf = 0; nf < 8; ++nf) {
        int o = wn * 64 + nf * 8 + (l & 3) * 2;
        float b0 = bias[o];
        float b1 = bias[o + 1];
#pragma unroll
        for (int mf = 0; mf < 2; ++mf) {
            acc[mf][nf][0] = b0;
            acc[mf][nf][1] = b1;
            acc[mf][nf][2] = b0;
            acc[mf][nf][3] = b1;
        }
    }

    // prologue: stage 0
    {
        build_a_half(0, bh, arow, rowbase);
        const float4* wg = reinterpret_cast<const float4*>(g_Wt);
        float4* ws = reinterpret_cast<float4*>(Wsm);
#pragma unroll
        for (int v = 0; v < 4; ++v) ws[tid + 256 * v] = wg[tid + 256 * v];
    }
    __syncthreads();

    for (int kt = 0; kt < NKT; ++kt) {
        const int s = kt & 1;

        // ---- build next tile into the other stage ----
        if (kt + 1 < NKT) {
            build_a_half(kt + 1, bh, arow + (s ^ 1) * A_STAGE_FLOATS, rowbase);
            const float4* wg = reinterpret_cast<const float4*>(
                g_Wt + (kt + 1) * W_STAGE_FLOATS);
            float4* ws = reinterpret_cast<float4*>(Wsm + (s ^ 1) * W_STAGE_FLOATS);
#pragma unroll
            for (int v = 0; v < 4; ++v) ws[tid + 256 * v] = wg[tid + 256 * v];
        }

        // ---- compute current tile: warp tile 32(M) x 64(N), k=32 ----
        const float* As = Asm + s * A_STAGE_FLOATS;
        const float* Ws = Wsm + s * W_STAGE_FLOATS;
        const float* ab = As + (wm * 32 + (l >> 2)) * AST + (l & 3);
        const float2* wb = reinterpret_cast<const float2*>(Ws) + (wn * 8) * 32 + l;

#pragma unroll
        for (int ks = 0; ks < 4; ++ks) {
            uint32_t a[2][4];
#pragma unroll
            for (int mf = 0; mf < 2; ++mf) {
                const float* p = ab + mf * (16 * AST) + ks * 8;
                a[mf][0] = __float_as_uint(p[0]);
                a[mf][1] = __float_as_uint(p[8 * AST]);
                a[mf][2] = __float_as_uint(p[4]);
                a[mf][3] = __float_as_uint(p[8 * AST + 4]);
            }
#pragma unroll
            for (int nf = 0; nf < 8; ++nf) {
                float2 bv = wb[ks * 512 + nf * 32];
                uint32_t b0 = __float_as_uint(bv.x);
                uint32_t b1 = __float_as_uint(bv.y);
#pragma unroll
                for (int mf = 0; mf < 2; ++mf)
                    mma8(acc[mf][nf], a[mf], b0, b1);
            }
        }
        __syncthreads();
    }

    // ---- epilogue: direct float2 stores (bias already folded) ----
#pragma unroll
    for (int mf = 0; mf < 2; ++mf) {
        int r0 = blockIdx.x * BM + wm * 32 + mf * 16 + (l >> 2);
#pragma unroll
        for (int nf = 0; nf < 8; ++nf) {
            int o = wn * 64 + nf * 8 + (l & 3) * 2;
            if (r0 < N_TOTAL) {
                float2 v = make_float2(acc[mf][nf][0], acc[mf][nf][1]);
                *reinterpret_cast<float2*>(out + (size_t)r0 * FILTERS + o) = v;
            }
            if (r0 + 8 < N_TOTAL) {
                float2 v = make_float2(acc[mf][nf][2], acc[mf][nf][3]);
                *reinterpret_cast<float2*>(out + (size_t)(r0 + 8) * FILTERS + o) = v;
            }
        }
    }
}

// ------------------------------------------------------------- launcher ----
extern "C" void kernel_launch(void* const* d_in, const int* in_sizes, int n_in,
                              void* d_out, int out_size) {
    const float* input = (const float*)d_in[0];   // (16,64,64,32)
    const float* sk    = (const float*)d_in[1];   // (288,8,128)
    const float* sc    = (const float*)d_in[2];   // (288,128)
    const float* bias  = (const float*)d_in[3];   // (128,)
    float* out = (float*)d_out;
    (void)in_sizes; (void)n_in; (void)out_size;

    static bool attr_done = false;
    if (!attr_done) {
        cudaFuncSetAttribute(kan_mma_kernel,
                             cudaFuncAttributeMaxDynamicSharedMemorySize, SMEM_TOTAL);
        attr_done = true;
    }

    fuse_weights<<<(K_TOTAL * FILTERS + 255) / 256, 256>>>(sk, sc);

    int blocks = (N_TOTAL + BM - 1) / BM;   // 481
    kan_mma_kernel<<<blocks, 256, SMEM_TOTAL>>>(input, bias, out);
}